// round 6
// baseline (speedup 1.0000x reference)
#include <cuda_runtime.h>
#include <cstdint>

#define N_ROWS   131072
#define K_CODES  512
#define D_DIM    64
#define ZQ_ELEMS (N_ROWS * D_DIM)
#define TILE_M   128
#define NTILES   (N_ROWS / TILE_M)
#define THREADS  256
#define GRID     152

// smem float offsets
#define O_CB   0          // 512*64 frag-permuted exact fp32 (128KB)
#define O_Z    32768      // 128*65
#define O_NRM  41088      // 512
#define O_ZN   41600      // 128
#define O_WIN  41728      // 128 int
#define O_LSTP 41856      // 128 u32 packed (row|k1<<7|k2<<16)
#define O_LSTF 41984      // 128 int
#define O_CNT  42112      // 2 ints
#define O_C    42114      // 1 float (eps slope)
#define SMEM_F 42116
#define SMEM_BYTES (SMEM_F * 4)

// frag-permuted word index for cb[k][d]
#define FW(k, d) ((k) * 64 + ((((d) & 3) + (k)) & 3) * 16 + ((d) >> 2))

__device__ __forceinline__ uint32_t f2tf32(float f) {
    uint32_t r;
    asm("cvt.rna.tf32.f32 %0, %1;" : "=r"(r) : "f"(f));
    return r;
}
__device__ __forceinline__ void mma_tf32(float& c0, float& c1, float& c2, float& c3,
                                         uint32_t a0, uint32_t a1, uint32_t a2, uint32_t a3,
                                         uint32_t b0, uint32_t b1) {
    asm volatile(
        "mma.sync.aligned.m16n8k8.row.col.f32.tf32.tf32.f32 "
        "{%0,%1,%2,%3}, {%4,%5,%6,%7}, {%8,%9}, {%0,%1,%2,%3};"
        : "+f"(c0), "+f"(c1), "+f"(c2), "+f"(c3)
        : "r"(a0), "r"(a1), "r"(a2), "r"(a3), "r"(b0), "r"(b1));
}

// 3-level min tracker insert of a (u,v) col-pair at codes (n0, n0+1)
__device__ __forceinline__ void ins3(float& m1, float& m2, float& m3,
                                     int& k1, int& k2, float u, float v, int n0) {
    bool pv = v < u;
    float lo = pv ? v : u, hi = pv ? u : v;
    int klo = pv ? n0 + 1 : n0, khi = pv ? n0 : n0 + 1;
    bool p1 = lo < m1, p2 = lo < m2, p3 = lo < m3;
    k2 = p1 ? k1 : (p2 ? klo : k2);
    m3 = p2 ? m2 : (p3 ? lo : m3);
    m2 = p1 ? m1 : (p2 ? lo : m2);
    k1 = p1 ? klo : k1;
    m1 = p1 ? lo : m1;
    bool q2 = hi < m2, q3 = hi < m3;
    m3 = q2 ? m2 : (q3 ? hi : m3);
    k2 = q2 ? khi : k2;
    m2 = q2 ? hi : m2;
}
// merge another lane's 3-tracker (index tie -> smaller k, matching first-min)
__device__ __forceinline__ void mrg3(float& m1, float& m2, float& m3,
                                     int& k1, int& k2, int off) {
    float b1 = __shfl_xor_sync(0xffffffffu, m1, off);
    float b2 = __shfl_xor_sync(0xffffffffu, m2, off);
    float b3 = __shfl_xor_sync(0xffffffffu, m3, off);
    int  bk1 = __shfl_xor_sync(0xffffffffu, k1, off);
    int  bk2 = __shfl_xor_sync(0xffffffffu, k2, off);
    bool p = (b1 < m1) || (b1 == m1 && bk1 < k1);
    float x = p ? m1 : b1;  int xk = p ? k1 : bk1;
    float y = p ? b2 : m2;  int yk = p ? bk2 : k2;
    float c1 = p ? b3 : m3;
    float c2 = p ? m2 : b2;
    if (p) { m1 = b1; k1 = bk1; }
    bool q = (x < y) || (x == y && xk < yk);
    m2 = q ? x : y;
    k2 = q ? xk : yk;
    m3 = fminf(q ? y : x, fminf(c1, c2));
}

__global__ void __launch_bounds__(THREADS, 1)
vq_mma(const float* __restrict__ z_e, const float* __restrict__ cb,
       float* __restrict__ out, float* __restrict__ fidx) {
    extern __shared__ float sh[];
    float* sCB  = sh + O_CB;
    float* sZ   = sh + O_Z;
    float* sNrm = sh + O_NRM;
    float* sZn  = sh + O_ZN;
    int*   sWin = (int*)(sh + O_WIN);
    uint32_t* sLP = (uint32_t*)(sh + O_LSTP);
    int*   sLF  = (int*)(sh + O_LSTF);
    int*   sCnt = (int*)(sh + O_CNT);
    float* sC   = sh + O_C;

    const int tid = threadIdx.x, wid = tid >> 5, lid = tid & 31;
    const int qid = lid & 3, gid = lid >> 2;

    // ---- stage codebook (exact fp32) into frag-permuted smem, once ----
    {
        const float4* src = (const float4*)cb;
#pragma unroll
        for (int i = 0; i < 32; i++) {
            int e = i * THREADS + tid;
            int k = e >> 4, j = e & 15;
            float4 v = src[e];
            sCB[FW(k, 4 * j + 0)] = v.x;
            sCB[FW(k, 4 * j + 1)] = v.y;
            sCB[FW(k, 4 * j + 2)] = v.z;
            sCB[FW(k, 4 * j + 3)] = v.w;
        }
    }
    __syncthreads();
    for (int k = tid; k < K_CODES; k += THREADS) {   // sequential-d norms
        float s = 0.0f;
#pragma unroll 8
        for (int d = 0; d < D_DIM; d++) {
            float v = sCB[FW(k, d)];
            s = __fadd_rn(s, __fmul_rn(v, v));
        }
        sNrm[k] = s;
    }
    __syncthreads();
    if (tid == 0) {   // eps slope: 4*(2^-10 + 2^-11) * ||e||max  (+margin)
        float mx = 0.0f;
        for (int k = 0; k < K_CODES; k++) mx = fmaxf(mx, sNrm[k]);
        *sC = 6.0e-3f * sqrtf(mx);
    }
    __syncthreads();

    for (int tile = blockIdx.x; tile < NTILES; tile += GRID) {
        __syncthreads();
        {   // stage z tile -> sZ[row][c] (pad 65)
            const int row0 = tile * TILE_M;
            const float4* z4 = (const float4*)(z_e + (long)(row0 >> 12) * 262144
                                               + (row0 & 4095));
#pragma unroll
            for (int m = 0; m < 8; m++) {
                int q = tid + THREADS * m;
                int c = q >> 5, i4 = q & 31;
                float4 v = z4[c * 1024 + i4];
                int r = i4 * 4;
                sZ[(r + 0) * 65 + c] = v.x;
                sZ[(r + 1) * 65 + c] = v.y;
                sZ[(r + 2) * 65 + c] = v.z;
                sZ[(r + 3) * 65 + c] = v.w;
            }
        }
        if (tid == 0) { sCnt[0] = 0; sCnt[1] = 0; }
        __syncthreads();
        if (tid < TILE_M) {
            const float* zr = sZ + tid * 65;
            float s = 0.0f;
#pragma unroll 8
            for (int d = 0; d < D_DIM; d++)
                s = __fadd_rn(s, __fmul_rn(zr[d], zr[d]));
            sZn[tid] = s;
        }
        __syncthreads();

        // ---- mma + fused 3-level argmin ----
        {
            const int rb = wid * 16;
            uint32_t A[8][4];
#pragma unroll
            for (int ks = 0; ks < 8; ks++) {
                const float* r0 = sZ + (rb + gid) * 65 + ks * 8 + qid;
                const float* r1 = r0 + 8 * 65;
                A[ks][0] = f2tf32(r0[0]);
                A[ks][1] = f2tf32(r1[0]);
                A[ks][2] = f2tf32(r0[4]);
                A[ks][3] = f2tf32(r1[4]);
            }
            float A1 = 3.4e38f, A2 = 3.4e38f, A3 = 3.4e38f;
            float B1 = 3.4e38f, B2 = 3.4e38f, B3 = 3.4e38f;
            int Ak1 = 0, Ak2 = 0, Bk1 = 0, Bk2 = 0;
            const float2* nrm2 = (const float2*)sNrm;
#pragma unroll 1
            for (int nt = 0; nt < 64; nt++) {
                const int k = nt * 8 + gid;
                const float4* bp = (const float4*)(sCB + k * 64 + ((qid + k) & 3) * 16);
                float4 w0 = bp[0], w1 = bp[1], w2 = bp[2], w3 = bp[3];
                float c0 = 0, c1 = 0, c2 = 0, c3 = 0;
                float d0 = 0, d1 = 0, d2 = 0, d3 = 0;
                mma_tf32(c0, c1, c2, c3, A[0][0], A[0][1], A[0][2], A[0][3],
                         __float_as_uint(w0.x), __float_as_uint(w0.y));
                mma_tf32(d0, d1, d2, d3, A[1][0], A[1][1], A[1][2], A[1][3],
                         __float_as_uint(w0.z), __float_as_uint(w0.w));
                mma_tf32(c0, c1, c2, c3, A[2][0], A[2][1], A[2][2], A[2][3],
                         __float_as_uint(w1.x), __float_as_uint(w1.y));
                mma_tf32(d0, d1, d2, d3, A[3][0], A[3][1], A[3][2], A[3][3],
                         __float_as_uint(w1.z), __float_as_uint(w1.w));
                mma_tf32(c0, c1, c2, c3, A[4][0], A[4][1], A[4][2], A[4][3],
                         __float_as_uint(w2.x), __float_as_uint(w2.y));
                mma_tf32(d0, d1, d2, d3, A[5][0], A[5][1], A[5][2], A[5][3],
                         __float_as_uint(w2.z), __float_as_uint(w2.w));
                mma_tf32(c0, c1, c2, c3, A[6][0], A[6][1], A[6][2], A[6][3],
                         __float_as_uint(w3.x), __float_as_uint(w3.y));
                mma_tf32(d0, d1, d2, d3, A[7][0], A[7][1], A[7][2], A[7][3],
                         __float_as_uint(w3.z), __float_as_uint(w3.w));
                float2 nk = nrm2[nt * 4 + qid];
                int n0 = nt * 8 + 2 * qid;
                float uA0 = __fmaf_rn(-2.0f, c0 + d0, nk.x);
                float uA1 = __fmaf_rn(-2.0f, c1 + d1, nk.y);
                float uB0 = __fmaf_rn(-2.0f, c2 + d2, nk.x);
                float uB1 = __fmaf_rn(-2.0f, c3 + d3, nk.y);
                ins3(A1, A2, A3, Ak1, Ak2, uA0, uA1, n0);
                ins3(B1, B2, B3, Bk1, Bk2, uB0, uB1, n0);
            }
            mrg3(A1, A2, A3, Ak1, Ak2, 1); mrg3(A1, A2, A3, Ak1, Ak2, 2);
            mrg3(B1, B2, B3, Bk1, Bk2, 1); mrg3(B1, B2, B3, Bk1, Bk2, 2);
            if (qid == 0) {
                int rA = rb + gid, rB = rA + 8;
                float epsA = __fmaf_rn(sqrtf(sZn[rA]), *sC, 1e-4f);
                float epsB = __fmaf_rn(sqrtf(sZn[rB]), *sC, 1e-4f);
                sWin[rA] = Ak1;
                sWin[rB] = Bk1;
                if (A3 - A1 < epsA)      sLF[atomicAdd(&sCnt[1], 1)] = rA;
                else if (A2 - A1 < epsA) sLP[atomicAdd(&sCnt[0], 1)] =
                    (uint32_t)rA | ((uint32_t)Ak1 << 7) | ((uint32_t)Ak2 << 16);
                if (B3 - B1 < epsB)      sLF[atomicAdd(&sCnt[1], 1)] = rB;
                else if (B2 - B1 < epsB) sLP[atomicAdd(&sCnt[0], 1)] =
                    (uint32_t)rB | ((uint32_t)Bk1 << 7) | ((uint32_t)Bk2 << 16);
            }
        }
        __syncthreads();

        // ---- pair refine: exact fp32 distances for {k1,k2} ----
        for (int i = tid; i < sCnt[0]; i += THREADS) {
            uint32_t pk = sLP[i];
            int row = pk & 127, ka = (pk >> 7) & 511, kb = (pk >> 16) & 511;
            const float* zr = sZ + row * 65;
            float zn = sZn[row];
            float sv[2]; int kk[2] = {ka, kb};
#pragma unroll
            for (int t = 0; t < 2; t++) {
                int k = kk[t];
                float aE = 0.0f, aO = 0.0f;
#pragma unroll 8
                for (int j = 0; j < 32; j++) {
                    aE = __fmaf_rn(zr[2 * j],     sCB[FW(k, 2 * j)],     aE);
                    aO = __fmaf_rn(zr[2 * j + 1], sCB[FW(k, 2 * j + 1)], aO);
                }
                sv[t] = __fadd_rn(__fadd_rn(zn, sNrm[k]),
                                  __fmul_rn(-2.0f, __fadd_rn(aE, aO)));
            }
            int win = (sv[1] < sv[0]) ? kb
                    : ((sv[0] < sv[1]) ? ka : min(ka, kb));
            sWin[row] = win;
        }
        // ---- full refine (rare): warp per row, exact scan of all 512 ----
        for (int fi = wid; fi < sCnt[1]; fi += 8) {
            const int row = sLF[fi];
            const float zn = sZn[row];
            const float* zr = sZ + row * 65;
            unsigned long long key = 0xffffffffffffffffULL;
#pragma unroll 1
            for (int kk2 = 0; kk2 < 16; kk2++) {
                int k = kk2 * 32 + lid;
                float ch0 = 0, ch1 = 0, ch2 = 0, ch3 = 0;
#pragma unroll
                for (int g = 0; g < 4; g++) {
                    int ql = (g - k) & 3;
                    const float4* ep = (const float4*)(sCB + k * 64 + g * 16);
                    float cg = 0.0f;
#pragma unroll
                    for (int u = 0; u < 4; u++) {
                        float4 e = ep[u];
                        cg = __fmaf_rn(zr[ql + 16 * u],      e.x, cg);
                        cg = __fmaf_rn(zr[ql + 16 * u + 4],  e.y, cg);
                        cg = __fmaf_rn(zr[ql + 16 * u + 8],  e.z, cg);
                        cg = __fmaf_rn(zr[ql + 16 * u + 12], e.w, cg);
                    }
                    if (g == 0) ch0 = cg; else if (g == 1) ch1 = cg;
                    else if (g == 2) ch2 = cg; else ch3 = cg;
                }
                float dot = __fadd_rn(__fadd_rn(ch0, ch1), __fadd_rn(ch2, ch3));
                float s = __fadd_rn(__fadd_rn(zn, sNrm[k]),
                                    __fmul_rn(-2.0f, dot));
                unsigned long long c =
                    ((unsigned long long)__float_as_uint(s) << 32) | (unsigned)k;
                if (c < key) key = c;
            }
#pragma unroll
            for (int off = 16; off > 0; off >>= 1) {
                unsigned long long o = __shfl_xor_sync(0xffffffffu, key, off);
                if (o < key) key = o;
            }
            if (lid == 0) sWin[row] = (int)(key & 0xffffffffu);
        }
        __syncthreads();

        // ---- fused gather write from gmem codebook (L2-hot) ----
        {
            const float4* cb4 = (const float4*)cb;
            float4* out4 = (float4*)out + (size_t)tile * 2048;
#pragma unroll
            for (int m = 0; m < 8; m++) {
                int q = tid + THREADS * m;
                out4[q] = cb4[sWin[q >> 4] * 16 + (q & 15)];
            }
            if (fidx && tid < TILE_M)
                fidx[tile * TILE_M + tid] = (float)sWin[tid];
        }
    }
}

extern "C" void kernel_launch(void* const* d_in, const int* in_sizes, int n_in,
                              void* d_out, int out_size) {
    const float* z_e = (const float*)d_in[0];
    const float* cb  = (const float*)d_in[1];
    if (n_in >= 2 && in_sizes[0] == K_CODES * D_DIM) {
        const float* t = z_e; z_e = cb; cb = t;
    }
    float* out = (float*)d_out;
    float* fidx = (out_size > ZQ_ELEMS) ? out + ZQ_ELEMS : nullptr;

    cudaFuncSetAttribute(vq_mma, cudaFuncAttributeMaxDynamicSharedMemorySize,
                         SMEM_BYTES);
    vq_mma<<<GRID, THREADS, SMEM_BYTES>>>(z_e, cb, out, fidx);
}

// round 7
// speedup vs baseline: 1.1583x; 1.1583x over previous
#include <cuda_runtime.h>
#include <cstdint>

#define N_ROWS   131072
#define K_CODES  512
#define D_DIM    64
#define ZQ_ELEMS (N_ROWS * D_DIM)
#define TILE_M   128
#define NTILES   (N_ROWS / TILE_M)
#define THREADS  256
#define GRID     152

// smem float offsets
#define O_BF   0          // 64nt * 512 words fragment-packed B (128KB)
#define O_Z    32768      // 128*65
#define O_NRM  41088      // 512
#define O_ZN   41600      // 128
#define O_WIN  41728      // 128 int
#define O_LSTP 41856      // 128 u32 packed (row|k1<<7|k2<<16)
#define O_LSTF 41984      // 128 int
#define O_CNT  42112      // 2 ints
#define O_C    42114      // 1 float (eps slope)
#define SMEM_F 42116
#define SMEM_BYTES (SMEM_F * 4)

__device__ __forceinline__ uint32_t f2tf32(float f) {
    uint32_t r;
    asm("cvt.rna.tf32.f32 %0, %1;" : "=r"(r) : "f"(f));
    return r;
}
__device__ __forceinline__ void mma_tf32(float& c0, float& c1, float& c2, float& c3,
                                         uint32_t a0, uint32_t a1, uint32_t a2, uint32_t a3,
                                         uint32_t b0, uint32_t b1) {
    asm volatile(
        "mma.sync.aligned.m16n8k8.row.col.f32.tf32.tf32.f32 "
        "{%0,%1,%2,%3}, {%4,%5,%6,%7}, {%8,%9}, {%0,%1,%2,%3};"
        : "+f"(c0), "+f"(c1), "+f"(c2), "+f"(c3)
        : "r"(a0), "r"(a1), "r"(a2), "r"(a3), "r"(b0), "r"(b1));
}

// 3-level min tracker insert of a (u,v) col-pair at codes (n0, n0+1)
__device__ __forceinline__ void ins3(float& m1, float& m2, float& m3,
                                     int& k1, int& k2, float u, float v, int n0) {
    bool pv = v < u;
    float lo = pv ? v : u, hi = pv ? u : v;
    int klo = pv ? n0 + 1 : n0, khi = pv ? n0 : n0 + 1;
    bool p1 = lo < m1, p2 = lo < m2, p3 = lo < m3;
    k2 = p1 ? k1 : (p2 ? klo : k2);
    m3 = p2 ? m2 : (p3 ? lo : m3);
    m2 = p1 ? m1 : (p2 ? lo : m2);
    k1 = p1 ? klo : k1;
    m1 = p1 ? lo : m1;
    bool q2 = hi < m2, q3 = hi < m3;
    m3 = q2 ? m2 : (q3 ? hi : m3);
    k2 = q2 ? khi : k2;
    m2 = q2 ? hi : m2;
}
__device__ __forceinline__ void mrg3(float& m1, float& m2, float& m3,
                                     int& k1, int& k2, int off) {
    float b1 = __shfl_xor_sync(0xffffffffu, m1, off);
    float b2 = __shfl_xor_sync(0xffffffffu, m2, off);
    float b3 = __shfl_xor_sync(0xffffffffu, m3, off);
    int  bk1 = __shfl_xor_sync(0xffffffffu, k1, off);
    int  bk2 = __shfl_xor_sync(0xffffffffu, k2, off);
    bool p = (b1 < m1) || (b1 == m1 && bk1 < k1);
    float x = p ? m1 : b1;  int xk = p ? k1 : bk1;
    float y = p ? b2 : m2;  int yk = p ? bk2 : k2;
    float c1 = p ? b3 : m3;
    float c2 = p ? m2 : b2;
    if (p) { m1 = b1; k1 = bk1; }
    bool q = (x < y) || (x == y && xk < yk);
    m2 = q ? x : y;
    k2 = q ? xk : yk;
    m3 = fminf(q ? y : x, fminf(c1, c2));
}

__global__ void __launch_bounds__(THREADS, 1)
vq_mma(const float* __restrict__ z_e, const float* __restrict__ cb,
       float* __restrict__ out, float* __restrict__ fidx) {
    extern __shared__ float sh[];
    float* sBF  = sh + O_BF;
    float* sZ   = sh + O_Z;
    float* sNrm = sh + O_NRM;
    float* sZn  = sh + O_ZN;
    int*   sWin = (int*)(sh + O_WIN);
    uint32_t* sLP = (uint32_t*)(sh + O_LSTP);
    int*   sLF  = (int*)(sh + O_LSTF);
    int*   sCnt = (int*)(sh + O_CNT);
    float* sC   = sh + O_C;

    const int tid = threadIdx.x, wid = tid >> 5, lid = tid & 31;
    const int qid = lid & 3, gid = lid >> 2;

    // ---- one-time: pack B fragments, chunked conflict-free layout ----
    // BF4[nt*128 + c*32 + lane] = { cb[k][d(j)] : j = c*4+u, u=0..3 }
    // j = 2*ks + h  ->  d = ks*8 + qid + h*4,  k = nt*8 + gid
    {
        float4* bf4 = (float4*)sBF;
        for (int e = tid; e < 8192; e += THREADS) {
            int nt = e >> 7, rem = e & 127;
            int c = rem >> 5, l = rem & 31;
            int g = l >> 2, q = l & 3;
            int k = nt * 8 + g;
            const float* ck = cb + k * D_DIM;
            float4 v;
            int j0 = c * 4;
            v.x = ck[((j0 + 0) >> 1) * 8 + q + ((j0 + 0) & 1) * 4];
            v.y = ck[((j0 + 1) >> 1) * 8 + q + ((j0 + 1) & 1) * 4];
            v.z = ck[((j0 + 2) >> 1) * 8 + q + ((j0 + 2) & 1) * 4];
            v.w = ck[((j0 + 3) >> 1) * 8 + q + ((j0 + 3) & 1) * 4];
            bf4[e] = v;
        }
    }
    // ---- norms (sequential-d, ref order) from gmem ----
    for (int k = tid; k < K_CODES; k += THREADS) {
        const float* e = cb + k * D_DIM;
        float s = 0.0f;
#pragma unroll 8
        for (int d = 0; d < D_DIM; d++)
            s = __fadd_rn(s, __fmul_rn(e[d], e[d]));
        sNrm[k] = s;
    }
    __syncthreads();
    if (tid == 0) {   // eps slope: ~4*(2^-10+2^-11)*||e||max with margin
        float mx = 0.0f;
        for (int k = 0; k < K_CODES; k++) mx = fmaxf(mx, sNrm[k]);
        *sC = 6.0e-3f * sqrtf(mx);
    }
    __syncthreads();

    for (int tile = blockIdx.x; tile < NTILES; tile += GRID) {
        __syncthreads();
        {   // stage z tile -> sZ[row][c] (pad 65)
            const int row0 = tile * TILE_M;
            const float4* z4 = (const float4*)(z_e + (long)(row0 >> 12) * 262144
                                               + (row0 & 4095));
#pragma unroll
            for (int m = 0; m < 8; m++) {
                int q = tid + THREADS * m;
                int c = q >> 5, i4 = q & 31;
                float4 v = z4[c * 1024 + i4];
                int r = i4 * 4;
                sZ[(r + 0) * 65 + c] = v.x;
                sZ[(r + 1) * 65 + c] = v.y;
                sZ[(r + 2) * 65 + c] = v.z;
                sZ[(r + 3) * 65 + c] = v.w;
            }
        }
        if (tid == 0) { sCnt[0] = 0; sCnt[1] = 0; }
        __syncthreads();
        if (tid < TILE_M) {
            const float* zr = sZ + tid * 65;
            float s = 0.0f;
#pragma unroll 8
            for (int d = 0; d < D_DIM; d++)
                s = __fadd_rn(s, __fmul_rn(zr[d], zr[d]));
            sZn[tid] = s;
        }
        __syncthreads();

        // ---- mma + fused 3-level argmin (warp: 16 rows x all 512 codes) ----
        {
            const int rb = wid * 16;
            uint32_t A[8][4];
#pragma unroll
            for (int ks = 0; ks < 8; ks++) {
                const float* r0 = sZ + (rb + gid) * 65 + ks * 8 + qid;
                const float* r1 = r0 + 8 * 65;
                A[ks][0] = f2tf32(r0[0]);
                A[ks][1] = f2tf32(r1[0]);
                A[ks][2] = f2tf32(r0[4]);
                A[ks][3] = f2tf32(r1[4]);
            }
            float A1 = 3.4e38f, A2 = 3.4e38f, A3 = 3.4e38f;
            float B1 = 3.4e38f, B2 = 3.4e38f, B3 = 3.4e38f;
            int Ak1 = 0, Ak2 = 0, Bk1 = 0, Bk2 = 0;
            const float2* nrm2 = (const float2*)sNrm;
            const float4* bf4 = (const float4*)sBF;
#pragma unroll 2
            for (int nt = 0; nt < 64; nt++) {
                float4 w0 = bf4[nt * 128 +   0 + lid];   // ks 0,1
                float4 w1 = bf4[nt * 128 +  32 + lid];   // ks 2,3
                float4 w2 = bf4[nt * 128 +  64 + lid];   // ks 4,5
                float4 w3 = bf4[nt * 128 +  96 + lid];   // ks 6,7
                float c0 = 0, c1 = 0, c2 = 0, c3 = 0;
                float d0 = 0, d1 = 0, d2 = 0, d3 = 0;
                mma_tf32(c0, c1, c2, c3, A[0][0], A[0][1], A[0][2], A[0][3],
                         __float_as_uint(w0.x), __float_as_uint(w0.y));
                mma_tf32(d0, d1, d2, d3, A[1][0], A[1][1], A[1][2], A[1][3],
                         __float_as_uint(w0.z), __float_as_uint(w0.w));
                mma_tf32(c0, c1, c2, c3, A[2][0], A[2][1], A[2][2], A[2][3],
                         __float_as_uint(w1.x), __float_as_uint(w1.y));
                mma_tf32(d0, d1, d2, d3, A[3][0], A[3][1], A[3][2], A[3][3],
                         __float_as_uint(w1.z), __float_as_uint(w1.w));
                mma_tf32(c0, c1, c2, c3, A[4][0], A[4][1], A[4][2], A[4][3],
                         __float_as_uint(w2.x), __float_as_uint(w2.y));
                mma_tf32(d0, d1, d2, d3, A[5][0], A[5][1], A[5][2], A[5][3],
                         __float_as_uint(w2.z), __float_as_uint(w2.w));
                mma_tf32(c0, c1, c2, c3, A[6][0], A[6][1], A[6][2], A[6][3],
                         __float_as_uint(w3.x), __float_as_uint(w3.y));
                mma_tf32(d0, d1, d2, d3, A[7][0], A[7][1], A[7][2], A[7][3],
                         __float_as_uint(w3.z), __float_as_uint(w3.w));
                float2 nk = nrm2[nt * 4 + qid];
                int n0 = nt * 8 + 2 * qid;
                float uA0 = __fmaf_rn(-2.0f, c0 + d0, nk.x);
                float uA1 = __fmaf_rn(-2.0f, c1 + d1, nk.y);
                float uB0 = __fmaf_rn(-2.0f, c2 + d2, nk.x);
                float uB1 = __fmaf_rn(-2.0f, c3 + d3, nk.y);
                ins3(A1, A2, A3, Ak1, Ak2, uA0, uA1, n0);
                ins3(B1, B2, B3, Bk1, Bk2, uB0, uB1, n0);
            }
            mrg3(A1, A2, A3, Ak1, Ak2, 1); mrg3(A1, A2, A3, Ak1, Ak2, 2);
            mrg3(B1, B2, B3, Bk1, Bk2, 1); mrg3(B1, B2, B3, Bk1, Bk2, 2);
            if (qid == 0) {
                int rA = rb + gid, rB = rA + 8;
                float epsA = __fmaf_rn(sqrtf(sZn[rA]), *sC, 1e-4f);
                float epsB = __fmaf_rn(sqrtf(sZn[rB]), *sC, 1e-4f);
                sWin[rA] = Ak1;
                sWin[rB] = Bk1;
                if (A3 - A1 < epsA)      sLF[atomicAdd(&sCnt[1], 1)] = rA;
                else if (A2 - A1 < epsA) sLP[atomicAdd(&sCnt[0], 1)] =
                    (uint32_t)rA | ((uint32_t)Ak1 << 7) | ((uint32_t)Ak2 << 16);
                if (B3 - B1 < epsB)      sLF[atomicAdd(&sCnt[1], 1)] = rB;
                else if (B2 - B1 < epsB) sLP[atomicAdd(&sCnt[0], 1)] =
                    (uint32_t)rB | ((uint32_t)Bk1 << 7) | ((uint32_t)Bk2 << 16);
            }
        }
        __syncthreads();

        // ---- pair refine: exact fp32 distances for {k1,k2} (gmem cb, L2) ----
        for (int i = tid; i < sCnt[0]; i += THREADS) {
            uint32_t pk = sLP[i];
            int row = pk & 127, ka = (pk >> 7) & 511, kb = (pk >> 16) & 511;
            const float* zr = sZ + row * 65;
            float zn = sZn[row];
            float sv[2]; int kk[2] = {ka, kb};
#pragma unroll
            for (int t = 0; t < 2; t++) {
                const float4* e4 = (const float4*)(cb + kk[t] * D_DIM);
                float aE = 0.0f, aO = 0.0f;
#pragma unroll
                for (int j = 0; j < 16; j++) {
                    float4 e = __ldg(e4 + j);
                    aE = __fmaf_rn(zr[4 * j],     e.x, aE);
                    aO = __fmaf_rn(zr[4 * j + 1], e.y, aO);
                    aE = __fmaf_rn(zr[4 * j + 2], e.z, aE);
                    aO = __fmaf_rn(zr[4 * j + 3], e.w, aO);
                }
                sv[t] = __fadd_rn(__fadd_rn(zn, sNrm[kk[t]]),
                                  __fmul_rn(-2.0f, __fadd_rn(aE, aO)));
            }
            sWin[row] = (sv[1] < sv[0]) ? kb
                      : ((sv[0] < sv[1]) ? ka : min(ka, kb));
        }
        // ---- full refine (rare): warp per row, exact scan of all 512 ----
        for (int fi = wid; fi < sCnt[1]; fi += 8) {
            const int row = sLF[fi];
            const float zn = sZn[row];
            const float* zr = sZ + row * 65;
            unsigned long long key = 0xffffffffffffffffULL;
#pragma unroll 1
            for (int kk2 = 0; kk2 < 16; kk2++) {
                int k = kk2 * 32 + lid;
                const float4* e4 = (const float4*)(cb + k * D_DIM);
                float aE = 0.0f, aO = 0.0f;
#pragma unroll
                for (int j = 0; j < 16; j++) {
                    float4 e = __ldg(e4 + j);
                    aE = __fmaf_rn(zr[4 * j],     e.x, aE);
                    aO = __fmaf_rn(zr[4 * j + 1], e.y, aO);
                    aE = __fmaf_rn(zr[4 * j + 2], e.z, aE);
                    aO = __fmaf_rn(zr[4 * j + 3], e.w, aO);
                }
                float s = __fadd_rn(__fadd_rn(zn, sNrm[k]),
                                    __fmul_rn(-2.0f, __fadd_rn(aE, aO)));
                unsigned long long c =
                    ((unsigned long long)__float_as_uint(s) << 32) | (unsigned)k;
                if (c < key) key = c;
            }
#pragma unroll
            for (int off = 16; off > 0; off >>= 1) {
                unsigned long long o = __shfl_xor_sync(0xffffffffu, key, off);
                if (o < key) key = o;
            }
            if (lid == 0) sWin[row] = (int)(key & 0xffffffffu);
        }
        __syncthreads();

        // ---- fused gather write from gmem codebook (L2-hot) ----
        {
            const float4* cb4 = (const float4*)cb;
            float4* out4 = (float4*)out + (size_t)tile * 2048;
#pragma unroll
            for (int m = 0; m < 8; m++) {
                int q = tid + THREADS * m;
                out4[q] = cb4[sWin[q >> 4] * 16 + (q & 15)];
            }
            if (fidx && tid < TILE_M)
                fidx[tile * TILE_M + tid] = (float)sWin[tid];
        }
    }
}

extern "C" void kernel_launch(void* const* d_in, const int* in_sizes, int n_in,
                              void* d_out, int out_size) {
    const float* z_e = (const float*)d_in[0];
    const float* cb  = (const float*)d_in[1];
    if (n_in >= 2 && in_sizes[0] == K_CODES * D_DIM) {
        const float* t = z_e; z_e = cb; cb = t;
    }
    float* out = (float*)d_out;
    float* fidx = (out_size > ZQ_ELEMS) ? out + ZQ_ELEMS : nullptr;

    cudaFuncSetAttribute(vq_mma, cudaFuncAttributeMaxDynamicSharedMemorySize,
                         SMEM_BYTES);
    vq_mma<<<GRID, THREADS, SMEM_BYTES>>>(z_e, cb, out, fidx);
}